// round 7
// baseline (speedup 1.0000x reference)
#include <cuda_runtime.h>
#include <cuda_bf16.h>

// ============================================================================
// TFCRNN teacher-forcing GRU. B=32, T=512, IN=256, H=2048, C=16.
// Persistent kernel, 128 CTAs x 512 thr (16 warps), 1 grid barrier/step.
//
// R7: latency-hiding rework of R6 (which was stall-bound: fma 24.5%, issue
// 21.8% with only 2 warps/SMSP and 72 ctasyncs/step):
//   - 16 warps/CTA -> 4 warps/SMSP; warp owns ONE hidden unit (3 W rows).
//   - 128-k W tiles, double-buffered with a SINGLE __syncthreads per tile
//     (18 syncs/step instead of 72).
//   - accumulators halved (8 f32x2) -> fits 512 thr at <=126 regs.
// W streamed once per step via smem, consumed as 2-address broadcast LDS.
// Lane = (kk = k-half, bh = batch mod 16); lane accumulates batches bh and
// bh+16 over its k-half; shfl_xor(16) folds halves. h/x quad-packed [k4][b].
//
// Identities: scheduled prob == 0.9 for all t -> flag = rand < 900;
//             sigmoid(v) > 0.5 <=> v > 0.
// ============================================================================

typedef unsigned long long ull;

#define BATCH 32
#define TSTEPS 512
#define INF 256
#define HID 2048
#define CLS 16
#define NCTA 128
#define NTHR 512
#define NTILE 18     // 2 x-tiles (256k) + 16 h-tiles (2048k), 128 k each
#define TILE_Q 1536  // 48 rows x 32 float4 per tile

__device__ float4 g_hq[2][512 * 32];       // h quad-packed [k4][b], ping-pong
__device__ float4 g_xq[TSTEPS * 64 * 32];  // x transposed [t][k4][b]
__device__ float g_tf[CLS * BATCH];
__device__ unsigned g_bar_count, g_bar_gen, g_tf_flag;

// ---------------- helpers ----------------------------------------------------
__device__ __forceinline__ ull ffma2(ull a, ull b, ull c) {
    ull d;
    asm("fma.rn.f32x2 %0, %1, %2, %3;" : "=l"(d) : "l"(a), "l"(b), "l"(c));
    return d;
}
__device__ __forceinline__ float2 unpack2(ull v) {
    float2 f;
    asm("mov.b64 {%0, %1}, %2;" : "=f"(f.x), "=f"(f.y) : "l"(v));
    return f;
}
__device__ __forceinline__ float sigmoidf_(float v) {
    return 1.0f / (1.0f + expf(-v));
}

// ---------------- grid barrier ----------------------------------------------
__device__ __forceinline__ void grid_barrier(unsigned& gen) {
    __syncthreads();
    if (threadIdx.x == 0) {
        __threadfence();
        unsigned arr = atomicAdd(&g_bar_count, 1u);
        if (arr == NCTA - 1) {
            g_bar_count = 0;
            __threadfence();
            atomicExch(&g_bar_gen, gen + 1);
        } else {
            unsigned g;
            do {
                asm volatile("ld.acquire.gpu.u32 %0, [%1];"
                             : "=r"(g) : "l"(&g_bar_gen) : "memory");
                if (g == gen) __nanosleep(32);
            } while (g == gen);
        }
        __threadfence();
    }
    gen++;
    __syncthreads();
}

// ---------------- reset ------------------------------------------------------
__global__ void reset_kernel() {
    int i = blockIdx.x * blockDim.x + threadIdx.x;
    if (i < 512 * 32) g_hq[0][i] = make_float4(0.f, 0.f, 0.f, 0.f);
    if (i < CLS * BATCH) g_tf[i] = 0.0f;
    if (i == 0) { g_bar_count = 0; g_bar_gen = 0; g_tf_flag = 0; }
}

// ---------------- per-tile MAC (warp owns 1 unit, 3 gate rows) ---------------
// op: quad-packed operand [32 k4][32 b]; sw: smem tile (48 rows x 32 float4)
__device__ __forceinline__ void tile_mac(const float4* __restrict__ op,
                                         const float4* __restrict__ sw,
                                         int wid, int kk, int bh, ull (&aR)[2],
                                         ull (&aZ)[2], ull (&aNI)[2]) {
    const float4* opl = op + kk * 16 * 32 + bh;  // lane's operand column base
    const float4* swR = sw + (0 * 16 + wid) * 32 + kk * 16;
    const float4* swZ = sw + (1 * 16 + wid) * 32 + kk * 16;
    const float4* swN = sw + (2 * 16 + wid) * 32 + kk * 16;
#pragma unroll 4
    for (int j2 = 0; j2 < 16; j2++) {
        ulonglong2 hA = *(const ulonglong2*)&opl[j2 * 32];
        ulonglong2 hB = *(const ulonglong2*)&opl[j2 * 32 + 16];
        ulonglong2 w;
        w = *(const ulonglong2*)&swR[j2];
        aR[0] = ffma2(hA.x, w.x, aR[0]);
        aR[0] = ffma2(hA.y, w.y, aR[0]);
        aR[1] = ffma2(hB.x, w.x, aR[1]);
        aR[1] = ffma2(hB.y, w.y, aR[1]);
        w = *(const ulonglong2*)&swZ[j2];
        aZ[0] = ffma2(hA.x, w.x, aZ[0]);
        aZ[0] = ffma2(hA.y, w.y, aZ[0]);
        aZ[1] = ffma2(hB.x, w.x, aZ[1]);
        aZ[1] = ffma2(hB.y, w.y, aZ[1]);
        w = *(const ulonglong2*)&swN[j2];
        aNI[0] = ffma2(hA.x, w.x, aNI[0]);
        aNI[0] = ffma2(hA.y, w.y, aNI[0]);
        aNI[1] = ffma2(hB.x, w.x, aNI[1]);
        aNI[1] = ffma2(hB.y, w.y, aNI[1]);
    }
}

// ---------------- persistent kernel -----------------------------------------
__global__ __launch_bounds__(NTHR, 1) void tfcrnn_persistent(
    const float* __restrict__ x, const float* __restrict__ y,
    const int* __restrict__ rand_vals, const float* __restrict__ W_ih,
    const float* __restrict__ W_hh, const float* __restrict__ b_ih,
    const float* __restrict__ b_hh, const float* __restrict__ W_cls,
    const float* __restrict__ b_cls, float* __restrict__ out) {
    const int tid = threadIdx.x;
    const int lane = tid & 31;
    const int wid = tid >> 5;  // 0..15, owns unit cta*16 + wid
    const int cta = blockIdx.x;
    const int kk = lane >> 4;  // k-half
    const int bh = lane & 15;  // batch (lane covers bh and bh+16)
    unsigned gen = 0;

    __shared__ float4 s_w[2][TILE_Q];
    __shared__ float s_cls[16][BATCH];

    // this thread's 3 W-fetch slots (fid = tid + j*512; 1536 = 48 rows x 32)
    int f_r[3], f_c[3];
#pragma unroll
    for (int j = 0; j < 3; j++) {
        int fid = tid + j * NTHR;
        f_r[j] = fid >> 5;   // row 0..47 (gate*16 + unit)
        f_c[j] = fid & 31;   // k4 col 0..31
    }

    // ---- one-time: transpose x into quad-packed g_xq ----
    for (int o = cta * NTHR + tid; o < TSTEPS * 64 * 32; o += NCTA * NTHR) {
        int b = o & 31, k4 = (o >> 5) & 63, tt = o >> 11;
        g_xq[o] = *(const float4*)&x[((size_t)b * TSTEPS + tt) * INF + k4 * 4];
    }
    grid_barrier(gen);

    const int u = cta * 16 + wid;  // this warp's hidden unit
    const int cta16 = cta * 16;
    const float bRc = b_ih[u] + b_hh[u];
    const float bZc = b_ih[HID + u] + b_hh[HID + u];
    const float bIc = b_ih[2 * HID + u];
    const float bNc = b_hh[2 * HID + u];
    const int tb = bh + 16 * kk;  // the batch this lane finalizes

    for (int t = 0; t < TSTEPS; t++) {
        const float4* __restrict__ hq_in = g_hq[t & 1];
        float4* __restrict__ hq_out = g_hq[(t + 1) & 1];

        ull aR[2] = {0, 0}, aZ[2] = {0, 0}, aI[2] = {0, 0}, aN[2] = {0, 0};

        // ---- prologue: LDG W tile 0 (x-tile, k-offset 0) into regs ----
        float4 nt[3];
#pragma unroll
        for (int j = 0; j < 3; j++) {
            int gate = f_r[j] >> 4, uu = f_r[j] & 15;
            nt[j] = *(const float4*)(W_ih +
                                     (size_t)(gate * HID + cta16 + uu) * 272 +
                                     f_c[j] * 4);
        }

        // ---- tile loop: 2 x-tiles + 16 h-tiles, single sync per tile ----
        for (int i = 0; i < NTILE; i++) {
            // STS tile i into buf[i&1] (consumers of this buf finished at
            // tile i-2, before the sync inside tile i-1)
#pragma unroll
            for (int j = 0; j < 3; j++)
                s_w[i & 1][f_r[j] * 32 + f_c[j]] = nt[j];
            __syncthreads();  // buf[i&1] ready for all warps
            if (i + 1 < NTILE) {
                const int ni = i + 1;
#pragma unroll
                for (int j = 0; j < 3; j++) {
                    int gate = f_r[j] >> 4, uu = f_r[j] & 15;
                    const float* src =
                        (ni < 2)
                            ? W_ih + (size_t)(gate * HID + cta16 + uu) * 272 +
                                  ni * 128 + f_c[j] * 4
                            : W_hh + (size_t)(gate * HID + cta16 + uu) * 2048 +
                                  (ni - 2) * 128 + f_c[j] * 4;
                    nt[j] = *(const float4*)src;  // hidden under tile_mac
                }
            }
            const float4* sw = s_w[i & 1];
            if (i < 2)
                tile_mac(g_xq + ((size_t)t * 64 + i * 32) * 32, sw, wid, kk,
                         bh, aR, aZ, aI);
            else
                tile_mac(hq_in + (size_t)(i - 2) * 32 * 32, sw, wid, kk, bh,
                         aR, aZ, aN);
        }

        // ---- fold f32x2 + combine k-halves via shfl ----
        float2 f;
        float v;
        f = unpack2(aR[0]); v = f.x + f.y;
        float fR0 = v + __shfl_xor_sync(0xffffffffu, v, 16);
        f = unpack2(aR[1]); v = f.x + f.y;
        float fR1 = v + __shfl_xor_sync(0xffffffffu, v, 16);
        f = unpack2(aZ[0]); v = f.x + f.y;
        float fZ0 = v + __shfl_xor_sync(0xffffffffu, v, 16);
        f = unpack2(aZ[1]); v = f.x + f.y;
        float fZ1 = v + __shfl_xor_sync(0xffffffffu, v, 16);
        f = unpack2(aI[0]); v = f.x + f.y;
        float fI0 = v + __shfl_xor_sync(0xffffffffu, v, 16);
        f = unpack2(aI[1]); v = f.x + f.y;
        float fI1 = v + __shfl_xor_sync(0xffffffffu, v, 16);
        f = unpack2(aN[0]); v = f.x + f.y;
        float fN0 = v + __shfl_xor_sync(0xffffffffu, v, 16);
        f = unpack2(aN[1]); v = f.x + f.y;
        float fN1 = v + __shfl_xor_sync(0xffffffffu, v, 16);

        // ---- wait for tf(t-1) (hidden under GEMV above) ----
        if (tid == 0) {
            unsigned thr = 16u * (unsigned)t, vv;
            do {
                asm volatile("ld.acquire.gpu.u32 %0, [%1];"
                             : "=r"(vv) : "l"(&g_tf_flag) : "memory");
                if (vv < thr) __nanosleep(32);
            } while (vv < thr);
            __threadfence();
        }
        __syncthreads();

        // ---- tf segment: cols 256..271 of W_ih for unit u, batch tb ----
        float tR = 0, tZ = 0, tI = 0;
#pragma unroll
        for (int j4 = 0; j4 < 4; j4++) {
            float4 wR = *(const float4*)&W_ih[(size_t)u * 272 + 256 + j4 * 4];
            float4 wZ =
                *(const float4*)&W_ih[(size_t)(HID + u) * 272 + 256 + j4 * 4];
            float4 wI = *(const float4*)&W_ih[(size_t)(2 * HID + u) * 272 +
                                              256 + j4 * 4];
#pragma unroll
            for (int jj = 0; jj < 4; jj++) {
                float tv = g_tf[(j4 * 4 + jj) * 32 + tb];
                tR = fmaf(tv, ((const float*)&wR)[jj], tR);
                tZ = fmaf(tv, ((const float*)&wZ)[jj], tZ);
                tI = fmaf(tv, ((const float*)&wI)[jj], tI);
            }
        }

        // ---- gates + state update (this lane: unit u, batch tb) ----
        {
            const int k4 = u >> 2, e = u & 3;
            float sR = (kk ? fR1 : fR0) + tR + bRc;
            float sZ = (kk ? fZ1 : fZ0) + tZ + bZc;
            float sI = (kk ? fI1 : fI0) + tI + bIc;
            float sN = (kk ? fN1 : fN0) + bNc;
            float hp = ((const float*)hq_in)[(size_t)(k4 * 32 + tb) * 4 + e];
            float r = sigmoidf_(sR);
            float z = sigmoidf_(sZ);
            float n = tanhf(sI + r * sN);
            float hn = (1.0f - z) * n + z * hp;
            ((float*)hq_out)[(size_t)(k4 * 32 + tb) * 4 + e] = hn;
        }

        grid_barrier(gen);  // h(t) complete & visible

        // ---- classifier + teacher forcing: CTA c < 16 owns class c ----
        if (cta < CLS) {
            const int c = cta;
            const int b = lane;
            float acc = 0.0f;
            const int k4b = wid * 32;
#pragma unroll 8
            for (int k4 = k4b; k4 < k4b + 32; k4++) {
                float4 hv = hq_out[k4 * 32 + b];
                float4 wv = *(const float4*)&W_cls[(size_t)c * HID + k4 * 4];
                acc = fmaf(hv.x, wv.x, acc);
                acc = fmaf(hv.y, wv.y, acc);
                acc = fmaf(hv.z, wv.z, acc);
                acc = fmaf(hv.w, wv.w, acc);
            }
            s_cls[wid][b] = acc;
            __syncthreads();
            if (wid == 0) {
                float tot = b_cls[c];
#pragma unroll
                for (int w = 0; w < 16; w++) tot += s_cls[w][b];
                out[((size_t)b * TSTEPS + t) * CLS + c] = tot;
                float pred = (tot > 0.0f) ? 1.0f : 0.0f;
                bool fl = rand_vals[t * BATCH + b] < 900;
                g_tf[c * 32 + b] =
                    fl ? y[((size_t)b * TSTEPS + t) * CLS + c] : pred;
            }
            __syncthreads();
            if (tid == 0) {
                __threadfence();
                atomicAdd(&g_tf_flag, 1u);
            }
        }
    }
}

// ---------------- launch ----------------------------------------------------
extern "C" void kernel_launch(void* const* d_in, const int* in_sizes, int n_in,
                              void* d_out, int out_size) {
    const float* x     = (const float*)d_in[0];
    const float* y     = (const float*)d_in[1];
    const int*   rv    = (const int*)d_in[2];
    const float* W_ih  = (const float*)d_in[3];
    const float* W_hh  = (const float*)d_in[4];
    const float* b_ih  = (const float*)d_in[5];
    const float* b_hh  = (const float*)d_in[6];
    const float* W_cls = (const float*)d_in[7];
    const float* b_cls = (const float*)d_in[8];
    float* out = (float*)d_out;

    reset_kernel<<<64, 256>>>();
    tfcrnn_persistent<<<NCTA, NTHR>>>(x, y, rv, W_ih, W_hh, b_ih, b_hh, W_cls,
                                      b_cls, out);
}

// round 10
// speedup vs baseline: 1.2547x; 1.2547x over previous
#include <cuda_runtime.h>

// ============================================================================
// TFCRNN teacher-forcing GRU. B=32, T=512, IN=256, H=2048, C=16.
// Persistent kernel, 128 CTAs x 384 thr (12 warps = 4 trios).
//
// R10 == R8 with the finalize-stage h indexing bug fixed (was writing local
// unit index u instead of global gu = cta*16+u -> all CTAs clobbered units
// 0..15; rel_err 0.99).
//
// Wavefront-minimal GEMV: warp computes a 16-row x 32-batch outer-product
// tile per k: 1 broadcast LDS.128 (W) + 1 LDG.128 (operand row, 128B) +
// 8 FFMA2 per lane per k. 4 trios of 3 warps each own disjoint 576-k ranges
// with private smem W double-buffers and per-trio named barriers; partial
// sums combined once per step through smem.
//
// W pre-packed per CTA into g_wc[cta][k][48] (rows: 16 R, 16 Z, 16 N).
// h stored [u][b] (128B rows); x pre-transposed to g_x2[t][k][b].
// N-gate keeps x-part (i_n) and h-part (h_n) separate via accX / s_partX.
//
// Identities: scheduled prob == 0.9 for all t -> flag = rand < 900;
//             sigmoid(v) > 0.5 <=> v > 0.
// ============================================================================

typedef unsigned long long ull;

#define BATCH 32
#define TSTEPS 512
#define INF 256
#define HID 2048
#define CLS 16
#define NCTA 128
#define NTHR 384
#define KTOT 2304  // 2048 h + 256 x
#define KTILE 64
#define TPT 9      // tiles per trio (9*64 = 576 k)
#define ROWS 48

__device__ float g_h[2][HID * BATCH];                    // [u][b]
__device__ float g_x2[TSTEPS * INF * BATCH];             // [t][k][b]
__device__ float g_wc[(size_t)NCTA * KTOT * ROWS];       // [cta][k][48]
__device__ float g_tf[CLS * BATCH];
__device__ unsigned g_bar_count, g_bar_gen, g_tf_flag;

// ---------------- helpers ----------------------------------------------------
__device__ __forceinline__ ull ffma2(ull a, ull b, ull c) {
    ull d;
    asm("fma.rn.f32x2 %0, %1, %2, %3;" : "=l"(d) : "l"(a), "l"(b), "l"(c));
    return d;
}
__device__ __forceinline__ ull dup2(float v) {
    ull r;
    asm("mov.b64 %0, {%1, %1};" : "=l"(r) : "f"(v));
    return r;
}
__device__ __forceinline__ float sigmoidf_(float v) {
    return 1.0f / (1.0f + expf(-v));
}

// ---------------- grid barrier (R3-proven) -----------------------------------
__device__ __forceinline__ void grid_barrier(unsigned& gen) {
    __syncthreads();
    if (threadIdx.x == 0) {
        __threadfence();
        unsigned arr = atomicAdd(&g_bar_count, 1u);
        if (arr == NCTA - 1) {
            g_bar_count = 0;
            __threadfence();
            atomicExch(&g_bar_gen, gen + 1);
        } else {
            unsigned g;
            do {
                asm volatile("ld.acquire.gpu.u32 %0, [%1];"
                             : "=r"(g) : "l"(&g_bar_gen) : "memory");
            } while (g == gen);
        }
        __threadfence();
    }
    gen++;
    __syncthreads();
}

// ---------------- reset ------------------------------------------------------
__global__ void reset_kernel() {
    int i = blockIdx.x * blockDim.x + threadIdx.x;
    if (i < HID * BATCH) g_h[0][i] = 0.0f;
    if (i < CLS * BATCH) g_tf[i] = 0.0f;
    if (i == 0) { g_bar_count = 0; g_bar_gen = 0; g_tf_flag = 0; }
}

// ---------------- 64-k tile MAC ----------------------------------------------
// sw: this lane's W base (s_wt tile + rb*16 + rg*4), stride 48 per k
// op: this lane's operand base (row + bg*4), stride 32 per k
__device__ __forceinline__ void mac64(const float* __restrict__ sw,
                                      const float* __restrict__ op,
                                      ull (&acc)[4][2]) {
#pragma unroll 4
    for (int k = 0; k < KTILE; k++) {
        float4 w4 = *(const float4*)(sw + k * ROWS);
        ulonglong2 hv = *(const ulonglong2*)(op + k * BATCH);
        ull w0 = dup2(w4.x), w1 = dup2(w4.y), w2 = dup2(w4.z), w3 = dup2(w4.w);
        acc[0][0] = ffma2(w0, hv.x, acc[0][0]);
        acc[0][1] = ffma2(w0, hv.y, acc[0][1]);
        acc[1][0] = ffma2(w1, hv.x, acc[1][0]);
        acc[1][1] = ffma2(w1, hv.y, acc[1][1]);
        acc[2][0] = ffma2(w2, hv.x, acc[2][0]);
        acc[2][1] = ffma2(w2, hv.y, acc[2][1]);
        acc[3][0] = ffma2(w3, hv.x, acc[3][0]);
        acc[3][1] = ffma2(w3, hv.y, acc[3][1]);
    }
}

// ---------------- persistent kernel -----------------------------------------
__global__ __launch_bounds__(NTHR, 1) void tfcrnn_persistent(
    const float* __restrict__ x, const float* __restrict__ y,
    const int* __restrict__ rand_vals, const float* __restrict__ W_ih,
    const float* __restrict__ W_hh, const float* __restrict__ b_ih,
    const float* __restrict__ b_hh, const float* __restrict__ W_cls,
    const float* __restrict__ b_cls, float* __restrict__ out) {
    const int tid = threadIdx.x;
    const int lane = tid & 31;
    const int wid = tid >> 5;     // 0..11
    const int cta = blockIdx.x;
    const int trio = wid / 3;     // 0..3 : k-range
    const int rb = wid % 3;       // row block (gate): 0=R 1=Z 2=N
    const int rg = lane >> 3;     // 4-row frag within block
    const int bg = lane & 7;      // 4-batch frag
    const int tit = tid - trio * 96;  // 0..95 within trio
    unsigned gen = 0;

    extern __shared__ float sm[];
    float* s_wt = sm;                                 // [4][2][KTILE*ROWS]
    float* s_part = sm + 4 * 2 * KTILE * ROWS;        // [4][48][32]
    float* s_partX = s_part + 4 * ROWS * BATCH;       // [48][32] (x-part)
    float* s_cls = s_partX + ROWS * BATCH;            // [8][32]

    // ---- one-time per launch: pack W for this CTA ----
    {
        float* wc = g_wc + (size_t)cta * KTOT * ROWS;
        for (int r = 0; r < ROWS; r++) {
            int gate = r >> 4, uu = r & 15;
            const float* rowH = W_hh + (size_t)(gate * HID + cta * 16 + uu) * HID;
            const float* rowX = W_ih + (size_t)(gate * HID + cta * 16 + uu) * 272;
            for (int k = tid; k < KTOT; k += NTHR)
                wc[(size_t)k * ROWS + r] = (k < HID) ? rowH[k] : rowX[k - HID];
        }
    }
    // ---- one-time: transpose x into g_x2[t][k][b] ----
    for (int o = cta * NTHR + tid; o < TSTEPS * INF * BATCH; o += NCTA * NTHR) {
        int b = o & 31, k = (o >> 5) & 255, tt = o >> 13;
        g_x2[o] = x[((size_t)b * TSTEPS + tt) * INF + k];
    }
    grid_barrier(gen);

    const float* wcb = g_wc + (size_t)cta * KTOT * ROWS;
    const int g0 = trio * TPT;

    for (int t = 0; t < TSTEPS; t++) {
        const float* __restrict__ hcur = g_h[t & 1];
        float* __restrict__ hnxt = g_h[(t + 1) & 1];
        const float* __restrict__ x2t = g_x2 + (size_t)t * INF * BATCH;

        ull acc[4][2], accX[4][2];
#pragma unroll
        for (int j = 0; j < 4; j++) {
            acc[j][0] = 0; acc[j][1] = 0; accX[j][0] = 0; accX[j][1] = 0;
        }

        // prologue: LDG tile g0 into regs
        float4 nt[8];
        {
            const float4* src = (const float4*)(wcb + (size_t)g0 * KTILE * ROWS);
#pragma unroll
            for (int j = 0; j < 8; j++) nt[j] = src[tit + j * 96];
        }

        // ---- per-trio tile pipeline (9 tiles, 1 named barrier each) ----
        for (int i = 0; i < TPT; i++) {
            const int g = g0 + i;
            float4* dst = (float4*)(s_wt + (trio * 2 + (i & 1)) * KTILE * ROWS);
#pragma unroll
            for (int j = 0; j < 8; j++) dst[tit + j * 96] = nt[j];
            asm volatile("bar.sync %0, %1;" ::"r"(trio + 1), "r"(96) : "memory");
            if (i + 1 < TPT) {
                const float4* s2 =
                    (const float4*)(wcb + (size_t)(g + 1) * KTILE * ROWS);
#pragma unroll
                for (int j = 0; j < 8; j++) nt[j] = s2[tit + j * 96];
            }
            const float* sw = s_wt + (trio * 2 + (i & 1)) * KTILE * ROWS +
                              rb * 16 + rg * 4;
            if (g < 32) {
                mac64(sw, hcur + (size_t)g * KTILE * BATCH + bg * 4, acc);
            } else {
                mac64(sw, x2t + (size_t)(g - 32) * KTILE * BATCH + bg * 4,
                      accX);
            }
        }

        // ---- write partials to smem ----
#pragma unroll
        for (int j = 0; j < 4; j++) {
#pragma unroll
            for (int p = 0; p < 2; p++) {
                int row = rb * 16 + rg * 4 + j;
                *(ull*)&s_part[((size_t)trio * ROWS + row) * BATCH + bg * 4 +
                               p * 2] = acc[j][p];
            }
        }
        if (trio == 3) {  // x-range owner: store x-part separately
#pragma unroll
            for (int j = 0; j < 4; j++)
#pragma unroll
                for (int p = 0; p < 2; p++) {
                    int row = rb * 16 + rg * 4 + j;
                    *(ull*)&s_partX[(size_t)row * BATCH + bg * 4 + p * 2] =
                        accX[j][p];
                }
        }
        __syncthreads();

        // ---- wait for tf(t-1) (hidden under GEMV) ----
        if (tid == 0) {
            unsigned thr = 16u * (unsigned)t, v;
            do {
                asm volatile("ld.acquire.gpu.u32 %0, [%1];"
                             : "=r"(v) : "l"(&g_tf_flag) : "memory");
            } while (v < thr);
            __threadfence();
        }
        __syncthreads();

        // ---- finalize 512 (u, b) items: gates + tf + state update ----
        for (int it = tid; it < 16 * BATCH; it += NTHR) {
            const int u = it >> 5, b = it & 31;
            const int gu = cta * 16 + u;
            float sR = s_partX[(size_t)u * BATCH + b];
            float sZ = s_partX[(size_t)(16 + u) * BATCH + b];
            float iN = s_partX[(size_t)(32 + u) * BATCH + b];
            float hN = 0.0f;
#pragma unroll
            for (int rr = 0; rr < 4; rr++) {
                sR += s_part[((size_t)rr * ROWS + u) * BATCH + b];
                sZ += s_part[((size_t)rr * ROWS + 16 + u) * BATCH + b];
                hN += s_part[((size_t)rr * ROWS + 32 + u) * BATCH + b];
            }
#pragma unroll
            for (int j = 0; j < CLS; j++) {
                float tfv = g_tf[j * 32 + b];
                sR = fmaf(tfv, W_ih[(size_t)gu * 272 + 256 + j], sR);
                sZ = fmaf(tfv, W_ih[(size_t)(HID + gu) * 272 + 256 + j], sZ);
                iN = fmaf(tfv, W_ih[(size_t)(2 * HID + gu) * 272 + 256 + j],
                          iN);
            }
            sR += b_ih[gu] + b_hh[gu];
            sZ += b_ih[HID + gu] + b_hh[HID + gu];
            iN += b_ih[2 * HID + gu];
            hN += b_hh[2 * HID + gu];
            float hp = hcur[(size_t)gu * 32 + b];   // FIXED: global unit index
            float r = sigmoidf_(sR);
            float z = sigmoidf_(sZ);
            float n = tanhf(iN + r * hN);
            hnxt[(size_t)gu * 32 + b] = (1.0f - z) * n + z * hp;  // FIXED
        }

        grid_barrier(gen);  // h(t) complete & visible

        // ---- classifier + teacher forcing: CTA c < 16 owns class c ----
        if (cta < CLS) {
            const int c = cta;
            if (wid < 8) {
                float a = 0.0f;
                const int u0 = wid * 256;
#pragma unroll 8
                for (int u = u0; u < u0 + 256; u++)
                    a = fmaf(hnxt[(size_t)u * 32 + lane],
                             W_cls[(size_t)c * HID + u], a);
                s_cls[wid * 32 + lane] = a;
            }
            __syncthreads();
            if (wid == 0) {
                float tot = b_cls[c];
#pragma unroll
                for (int w = 0; w < 8; w++) tot += s_cls[w * 32 + lane];
                const int b = lane;
                out[((size_t)b * TSTEPS + t) * CLS + c] = tot;
                float pred = (tot > 0.0f) ? 1.0f : 0.0f;
                bool fl = rand_vals[t * BATCH + b] < 900;
                g_tf[c * 32 + b] =
                    fl ? y[((size_t)b * TSTEPS + t) * CLS + c] : pred;
            }
            __syncthreads();
            if (tid == 0) {
                __threadfence();
                atomicAdd(&g_tf_flag, 1u);
            }
        }
    }
}

// ---------------- launch ----------------------------------------------------
extern "C" void kernel_launch(void* const* d_in, const int* in_sizes, int n_in,
                              void* d_out, int out_size) {
    const float* x     = (const float*)d_in[0];
    const float* y     = (const float*)d_in[1];
    const int*   rv    = (const int*)d_in[2];
    const float* W_ih  = (const float*)d_in[3];
    const float* W_hh  = (const float*)d_in[4];
    const float* b_ih  = (const float*)d_in[5];
    const float* b_hh  = (const float*)d_in[6];
    const float* W_cls = (const float*)d_in[7];
    const float* b_cls = (const float*)d_in[8];
    float* out = (float*)d_out;

    const int smem_bytes =
        (4 * 2 * KTILE * ROWS + 4 * ROWS * BATCH + ROWS * BATCH + 8 * BATCH) *
        (int)sizeof(float);
    cudaFuncSetAttribute(tfcrnn_persistent,
                         cudaFuncAttributeMaxDynamicSharedMemorySize,
                         smem_bytes);

    reset_kernel<<<128, 512>>>();
    tfcrnn_persistent<<<NCTA, NTHR, smem_bytes>>>(
        x, y, rv, W_ih, W_hh, b_ih, b_hh, W_cls, b_cls, out);
}

// round 13
// speedup vs baseline: 1.2598x; 1.0041x over previous
#include <cuda_runtime.h>

// ============================================================================
// TFCRNN teacher-forcing GRU. B=32, T=512, IN=256, H=2048, C=16.
// Persistent kernel, 128 CTAs x 384 thr (12 warps = 4 trios).
//
// R11 = R10 + latency fixes:
//  (1) depth-4 LDG prefetch ring in the MAC inner loop (R10 stalled on the
//      250-cyc L2 operand load every iteration: MLP 4 < latency).
//  (2) x-GEMV (12.5% of FLOPs) precomputed for ALL t at kernel start into
//      g_gx[cta][t][48][32]; serial loop is pure 2048-k h-GEMV (8 tiles/trio).
//  (3) cls dual accumulators.
//
// Warp computes a 16-row x 32-batch outer-product tile per k:
// 1 broadcast LDS.128 (W) + 1 LDG.128 (operand row) + 8 FFMA2 per lane per k.
// 4 trios of 3 warps own disjoint 512-k ranges with private smem W double
// buffers + per-trio named barriers; partials combined once per step in smem.
//
// Identities: scheduled prob == 0.9 for all t -> flag = rand < 900;
//             sigmoid(v) > 0.5 <=> v > 0.
// ============================================================================

typedef unsigned long long ull;

#define BATCH 32
#define TSTEPS 512
#define INF 256
#define HID 2048
#define CLS 16
#define NCTA 128
#define NTHR 384
#define KTOT 2304  // 2048 h + 256 x (packed W layout)
#define KTILE 64
#define TPT 8      // h tiles per trio (8*64 = 512 k; 4 trios = 2048)
#define ROWS 48

__device__ float g_h[2][HID * BATCH];                          // [u][b]
__device__ float g_x2[TSTEPS * INF * BATCH];                   // [t][k][b]
__device__ float g_wc[(size_t)NCTA * KTOT * ROWS];             // [cta][k][48]
__device__ float g_gx[(size_t)NCTA * TSTEPS * ROWS * BATCH];   // [cta][t][48][32]
__device__ float g_tf[CLS * BATCH];
__device__ unsigned g_bar_count, g_bar_gen, g_tf_flag;

// ---------------- helpers ----------------------------------------------------
__device__ __forceinline__ ull ffma2(ull a, ull b, ull c) {
    ull d;
    asm("fma.rn.f32x2 %0, %1, %2, %3;" : "=l"(d) : "l"(a), "l"(b), "l"(c));
    return d;
}
__device__ __forceinline__ ull dup2(float v) {
    ull r;
    asm("mov.b64 %0, {%1, %1};" : "=l"(r) : "f"(v));
    return r;
}
__device__ __forceinline__ float sigmoidf_(float v) {
    return 1.0f / (1.0f + expf(-v));
}

// ---------------- grid barrier (R3-proven) -----------------------------------
__device__ __forceinline__ void grid_barrier(unsigned& gen) {
    __syncthreads();
    if (threadIdx.x == 0) {
        __threadfence();
        unsigned arr = atomicAdd(&g_bar_count, 1u);
        if (arr == NCTA - 1) {
            g_bar_count = 0;
            __threadfence();
            atomicExch(&g_bar_gen, gen + 1);
        } else {
            unsigned g;
            do {
                asm volatile("ld.acquire.gpu.u32 %0, [%1];"
                             : "=r"(g) : "l"(&g_bar_gen) : "memory");
            } while (g == gen);
        }
        __threadfence();
    }
    gen++;
    __syncthreads();
}

// ---------------- reset ------------------------------------------------------
__global__ void reset_kernel() {
    int i = blockIdx.x * blockDim.x + threadIdx.x;
    if (i < HID * BATCH) g_h[0][i] = 0.0f;
    if (i < CLS * BATCH) g_tf[i] = 0.0f;
    if (i == 0) { g_bar_count = 0; g_bar_gen = 0; g_tf_flag = 0; }
}

// ---------------- 64-k tile MAC with depth-4 LDG prefetch ring ---------------
// sw: lane's W base (tile base + rb*16 + rg*4), stride ROWS per k (smem or gmem)
// op: lane's operand base (tile row base + bg*4), stride BATCH per k (gmem)
__device__ __forceinline__ void mac64pf(const float* __restrict__ sw,
                                        const float* __restrict__ op,
                                        ull (&acc)[4][2]) {
    ulonglong2 o[4];
#pragma unroll
    for (int j = 0; j < 4; j++)
        o[j] = *(const ulonglong2*)(op + j * BATCH);
#pragma unroll
    for (int kb = 0; kb < KTILE; kb += 4) {
        ulonglong2 o2[4];
        if (kb + 4 < KTILE) {
#pragma unroll
            for (int j = 0; j < 4; j++)
                o2[j] = *(const ulonglong2*)(op + (kb + 4 + j) * BATCH);
        }
#pragma unroll
        for (int j = 0; j < 4; j++) {
            float4 w4 = *(const float4*)(sw + (kb + j) * ROWS);
            ull w0 = dup2(w4.x), w1 = dup2(w4.y);
            ull w2 = dup2(w4.z), w3 = dup2(w4.w);
            acc[0][0] = ffma2(w0, o[j].x, acc[0][0]);
            acc[0][1] = ffma2(w0, o[j].y, acc[0][1]);
            acc[1][0] = ffma2(w1, o[j].x, acc[1][0]);
            acc[1][1] = ffma2(w1, o[j].y, acc[1][1]);
            acc[2][0] = ffma2(w2, o[j].x, acc[2][0]);
            acc[2][1] = ffma2(w2, o[j].y, acc[2][1]);
            acc[3][0] = ffma2(w3, o[j].x, acc[3][0]);
            acc[3][1] = ffma2(w3, o[j].y, acc[3][1]);
        }
        if (kb + 4 < KTILE) {
#pragma unroll
            for (int j = 0; j < 4; j++) o[j] = o2[j];
        }
    }
}

// ---------------- persistent kernel -----------------------------------------
__global__ __launch_bounds__(NTHR, 1) void tfcrnn_persistent(
    const float* __restrict__ x, const float* __restrict__ y,
    const int* __restrict__ rand_vals, const float* __restrict__ W_ih,
    const float* __restrict__ W_hh, const float* __restrict__ b_ih,
    const float* __restrict__ b_hh, const float* __restrict__ W_cls,
    const float* __restrict__ b_cls, float* __restrict__ out) {
    const int tid = threadIdx.x;
    const int lane = tid & 31;
    const int wid = tid >> 5;     // 0..11
    const int cta = blockIdx.x;
    const int trio = wid / 3;     // 0..3 : k-range
    const int rb = wid % 3;       // row block (gate): 0=R 1=Z 2=N
    const int rg = lane >> 3;     // 4-row frag within block
    const int bg = lane & 7;      // 4-batch frag
    const int tit = tid - trio * 96;  // 0..95 within trio
    unsigned gen = 0;

    extern __shared__ float sm[];
    float* s_wt = sm;                            // [4][2][KTILE*ROWS]
    float* s_part = sm + 4 * 2 * KTILE * ROWS;   // [4][48][32]
    float* s_cls = s_part + 4 * ROWS * BATCH;    // [8][32]

    // ---- one-time: pack W for this CTA ----
    {
        float* wc = g_wc + (size_t)cta * KTOT * ROWS;
        for (int r = 0; r < ROWS; r++) {
            int gate = r >> 4, uu = r & 15;
            const float* rowH = W_hh + (size_t)(gate * HID + cta * 16 + uu) * HID;
            const float* rowX = W_ih + (size_t)(gate * HID + cta * 16 + uu) * 272;
            for (int k = tid; k < KTOT; k += NTHR)
                wc[(size_t)k * ROWS + r] = (k < HID) ? rowH[k] : rowX[k - HID];
        }
    }
    // ---- one-time: transpose x into g_x2[t][k][b] ----
    for (int o = cta * NTHR + tid; o < TSTEPS * INF * BATCH; o += NCTA * NTHR) {
        int b = o & 31, k = (o >> 5) & 255, tt = o >> 13;
        g_x2[o] = x[((size_t)b * TSTEPS + tt) * INF + k];
    }
    grid_barrier(gen);

    const float* wcb = g_wc + (size_t)cta * KTOT * ROWS;

    // ---- one-time: x-gate precompute gx[t][48][32] (own CTA only) ----
    for (int tt = wid; tt < TSTEPS; tt += 12) {
        const float* x2t = g_x2 + (size_t)tt * INF * BATCH;
        float* gxt = g_gx + ((size_t)cta * TSTEPS + tt) * ROWS * BATCH;
        for (int rbp = 0; rbp < 3; rbp++) {
            ull acc[4][2];
#pragma unroll
            for (int j = 0; j < 4; j++) { acc[j][0] = 0; acc[j][1] = 0; }
            const float* wp = wcb + (size_t)HID * ROWS + rbp * 16 + rg * 4;
#pragma unroll
            for (int c = 0; c < 4; c++)
                mac64pf(wp + (size_t)c * KTILE * ROWS,
                        x2t + (size_t)c * KTILE * BATCH + bg * 4, acc);
#pragma unroll
            for (int j = 0; j < 4; j++)
#pragma unroll
                for (int p = 0; p < 2; p++)
                    *(ull*)&gxt[(size_t)(rbp * 16 + rg * 4 + j) * BATCH +
                                bg * 4 + p * 2] = acc[j][p];
        }
    }
    // no barrier needed: gx is produced and consumed by the same CTA

    const int g0 = trio * TPT;

    for (int t = 0; t < TSTEPS; t++) {
        const float* __restrict__ hcur = g_h[t & 1];
        float* __restrict__ hnxt = g_h[(t + 1) & 1];

        ull acc[4][2];
#pragma unroll
        for (int j = 0; j < 4; j++) { acc[j][0] = 0; acc[j][1] = 0; }

        // prologue: LDG W tile g0 into regs
        float4 nt[8];
        {
            const float4* src = (const float4*)(wcb + (size_t)g0 * KTILE * ROWS);
#pragma unroll
            for (int j = 0; j < 8; j++) nt[j] = src[tit + j * 96];
        }

        // ---- per-trio tile pipeline (8 h-tiles, 1 named barrier each) ----
        for (int i = 0; i < TPT; i++) {
            const int g = g0 + i;
            float4* dst = (float4*)(s_wt + (trio * 2 + (i & 1)) * KTILE * ROWS);
#pragma unroll
            for (int j = 0; j < 8; j++) dst[tit + j * 96] = nt[j];
            asm volatile("bar.sync %0, %1;" ::"r"(trio + 1), "r"(96) : "memory");
            if (i + 1 < TPT) {
                const float4* s2 =
                    (const float4*)(wcb + (size_t)(g + 1) * KTILE * ROWS);
#pragma unroll
                for (int j = 0; j < 8; j++) nt[j] = s2[tit + j * 96];
            }
            mac64pf(s_wt + (trio * 2 + (i & 1)) * KTILE * ROWS + rb * 16 +
                        rg * 4,
                    hcur + (size_t)g * KTILE * BATCH + bg * 4, acc);
        }

        // ---- write partials to smem ----
#pragma unroll
        for (int j = 0; j < 4; j++)
#pragma unroll
            for (int p = 0; p < 2; p++) {
                int row = rb * 16 + rg * 4 + j;
                *(ull*)&s_part[((size_t)trio * ROWS + row) * BATCH + bg * 4 +
                               p * 2] = acc[j][p];
            }
        __syncthreads();

        // ---- wait for tf(t-1) (hidden under GEMV) ----
        if (tid == 0) {
            unsigned thr = 16u * (unsigned)t, v;
            do {
                asm volatile("ld.acquire.gpu.u32 %0, [%1];"
                             : "=r"(v) : "l"(&g_tf_flag) : "memory");
            } while (v < thr);
            __threadfence();
        }
        __syncthreads();

        // ---- finalize 512 (u, b) items: gates + tf + state update ----
        const float* gxt = g_gx + ((size_t)cta * TSTEPS + t) * ROWS * BATCH;
        for (int it = tid; it < 16 * BATCH; it += NTHR) {
            const int u = it >> 5, b = it & 31;
            const int gu = cta * 16 + u;
            float sR = gxt[(size_t)u * BATCH + b];
            float sZ = gxt[(size_t)(16 + u) * BATCH + b];
            float iN = gxt[(size_t)(32 + u) * BATCH + b];
            float hN = 0.0f;
#pragma unroll
            for (int rr = 0; rr < 4; rr++) {
                sR += s_part[((size_t)rr * ROWS + u) * BATCH + b];
                sZ += s_part[((size_t)rr * ROWS + 16 + u) * BATCH + b];
                hN += s_part[((size_t)rr * ROWS + 32 + u) * BATCH + b];
            }
#pragma unroll
            for (int j = 0; j < CLS; j++) {
                float tfv = g_tf[j * 32 + b];
                sR = fmaf(tfv, W_ih[(size_t)gu * 272 + 256 + j], sR);
                sZ = fmaf(tfv, W_ih[(size_t)(HID + gu) * 272 + 256 + j], sZ);
                iN = fmaf(tfv, W_ih[(size_t)(2 * HID + gu) * 272 + 256 + j],
                          iN);
            }
            sR += b_ih[gu] + b_hh[gu];
            sZ += b_ih[HID + gu] + b_hh[HID + gu];
            iN += b_ih[2 * HID + gu];
            hN += b_hh[2 * HID + gu];
            float hp = hcur[(size_t)gu * 32 + b];
            float r = sigmoidf_(sR);
            float z = sigmoidf_(sZ);
            float n = tanhf(iN + r * hN);
            hnxt[(size_t)gu * 32 + b] = (1.0f - z) * n + z * hp;
        }

        grid_barrier(gen);  // h(t) complete & visible

        // ---- classifier + teacher forcing: CTA c < 16 owns class c ----
        if (cta < CLS) {
            const int c = cta;
            if (wid < 8) {
                float a0 = 0.0f, a1 = 0.0f;
                const int u0 = wid * 256;
#pragma unroll 8
                for (int u = u0; u < u0 + 256; u += 2) {
                    a0 = fmaf(hnxt[(size_t)u * 32 + lane],
                              W_cls[(size_t)c * HID + u], a0);
                    a1 = fmaf(hnxt[(size_t)(u + 1) * 32 + lane],
                              W_cls[(size_t)c * HID + u + 1], a1);
                }
                s_cls[wid * 32 + lane] = a0 + a1;
            }
            __syncthreads();
            if (wid == 0) {
                float tot = b_cls[c];
#pragma unroll
                for (int w = 0; w < 8; w++) tot += s_cls[w * 32 + lane];
                const int b = lane;
                out[((size_t)b * TSTEPS + t) * CLS + c] = tot;
                float pred = (tot > 0.0f) ? 1.0f : 0.0f;
                bool fl = rand_vals[t * BATCH + b] < 900;
                g_tf[c * 32 + b] =
                    fl ? y[((size_t)b * TSTEPS + t) * CLS + c] : pred;
            }
            __syncthreads();
            if (tid == 0) {
                __threadfence();
                atomicAdd(&g_tf_flag, 1u);
            }
        }
    }
}

// ---------------- launch ----------------------------------------------------
extern "C" void kernel_launch(void* const* d_in, const int* in_sizes, int n_in,
                              void* d_out, int out_size) {
    const float* x     = (const float*)d_in[0];
    const float* y     = (const float*)d_in[1];
    const int*   rv    = (const int*)d_in[2];
    const float* W_ih  = (const float*)d_in[3];
    const float* W_hh  = (const float*)d_in[4];
    const float* b_ih  = (const float*)d_in[5];
    const float* b_hh  = (const float*)d_in[6];
    const float* W_cls = (const float*)d_in[7];
    const float* b_cls = (const float*)d_in[8];
    float* out = (float*)d_out;

    const int smem_bytes =
        (4 * 2 * KTILE * ROWS + 4 * ROWS * BATCH + 8 * BATCH) *
        (int)sizeof(float);
    cudaFuncSetAttribute(tfcrnn_persistent,
                         cudaFuncAttributeMaxDynamicSharedMemorySize,
                         smem_bytes);

    reset_kernel<<<128, 512>>>();
    tfcrnn_persistent<<<NCTA, NTHR, smem_bytes>>>(
        x, y, rv, W_ih, W_hh, b_ih, b_hh, W_cls, b_cls, out);
}

// round 17
// speedup vs baseline: 1.8644x; 1.4800x over previous
#include <cuda_runtime.h>
#include <cuda_bf16.h>
#include <cstdint>

// ============================================================================
// TFCRNN teacher-forcing GRU. B=32, T=512, IN=256, H=2048, C=16.
// R16: tensor cores via baseline-PTX mma.sync.m16n8k16 (bf16) + ldmatrix
// (tcgen05 is unavailable: harness compiles through compute_103, no 'a').
//
// 128 persistent CTAs x 384 thr (12 warps). CTA owns 16 units; A = 48 rows
// [R|Z|N] x K=2304 (2048 h-k + 256 x-k). Warp (mt = wid%3, nt = wid/3)
// computes D[16x8]: dH over h-chunks, dX over x-chunks (N-gate h/x kept
// separate; R/Z sum dH+dX). fp32 accuracy: bf16 hi/lo split, 3 products.
// W prepacked once to per-chunk row-major bf16 planes (g_wA); per-step smem
// fills are linear float4 copies (272B pitch -> conflict-free ldmatrix).
// Single-sync double buffer (R7-proven). h -> bf16 hi/lo chunks in finalize.
// Finalize/tf/cls/grid-barrier = R10/R13-proven fp32 code.
//
// Identities: scheduled prob == 0.9 for all t -> flag = rand < 900;
//             sigmoid(v) > 0.5 <=> v > 0.
// ============================================================================

typedef unsigned long long ull;

#define BATCH 32
#define TSTEPS 512
#define INF 256
#define HID 2048
#define CLS 16
#define NCTA 128
#define NTHR 384
#define NCH 18  // 16 h-chunks + 2 x-chunks, 128 k each

// smem byte offsets (272B row pitch: 68 words == 4 mod 32 -> ldmatrix clean)
#define SA(p, v) (((p) * 2 + (v)) * 13056)            // 48 rows x 272B
#define SB(p, v) (52224 + ((p) * 2 + (v)) * 8704)     // 32 rows x 272B
#define SP 87040                                      // 64 x 32 f32
#define SCLS 95232                                    // 8 x 32 f32
#define SMEM_SZ 96512

__device__ __nv_bfloat16 g_wA[(size_t)NCTA * NCH * 2 * 6144];  // [cta][ch][pl][48*128]
__device__ __nv_bfloat16 g_xB[(size_t)TSTEPS * 2 * 2 * 4096];  // [t][cx][pl][32*128]
__device__ __nv_bfloat16 g_hB[2][16 * 2 * 4096];               // [buf][ch][pl][b*128+kl]
__device__ float g_h[2][HID * BATCH];                          // [u*32+b]
__device__ float g_tf[CLS * BATCH];
__device__ unsigned g_bar_count, g_bar_gen, g_tf_flag;

// ---------------- mma / ldmatrix helpers -------------------------------------
__device__ __forceinline__ void ldsm_x4(uint32_t* r, uint32_t addr) {
    asm volatile("ldmatrix.sync.aligned.m8n8.x4.shared.b16 {%0,%1,%2,%3}, [%4];"
                 : "=r"(r[0]), "=r"(r[1]), "=r"(r[2]), "=r"(r[3])
                 : "r"(addr));
}
__device__ __forceinline__ void ldsm_x2(uint32_t* r, uint32_t addr) {
    asm volatile("ldmatrix.sync.aligned.m8n8.x2.shared.b16 {%0,%1}, [%2];"
                 : "=r"(r[0]), "=r"(r[1])
                 : "r"(addr));
}
__device__ __forceinline__ void mma16816(float* d, const uint32_t* a,
                                         const uint32_t* b) {
    asm volatile(
        "mma.sync.aligned.m16n8k16.row.col.f32.bf16.bf16.f32 "
        "{%0,%1,%2,%3}, {%4,%5,%6,%7}, {%8,%9}, {%0,%1,%2,%3};"
        : "+f"(d[0]), "+f"(d[1]), "+f"(d[2]), "+f"(d[3])
        : "r"(a[0]), "r"(a[1]), "r"(a[2]), "r"(a[3]), "r"(b[0]), "r"(b[1]));
}
__device__ __forceinline__ float sigmoidf_(float v) {
    return 1.0f / (1.0f + expf(-v));
}

// 128-k chunk: 8 k-steps of (ldsm aHi/aLo/bHi/bLo + 3 mma), accumulate in d
__device__ __forceinline__ void chunk_mma(uint32_t aHiB, uint32_t aLoB,
                                          uint32_t bHiB, uint32_t bLoB,
                                          float* d) {
#pragma unroll
    for (int s = 0; s < 8; s++) {
        uint32_t ah[4], al[4], bh[2], bl[2];
        ldsm_x4(ah, aHiB + s * 32);
        ldsm_x4(al, aLoB + s * 32);
        ldsm_x2(bh, bHiB + s * 32);
        ldsm_x2(bl, bLoB + s * 32);
        mma16816(d, ah, bh);
        mma16816(d, ah, bl);
        mma16816(d, al, bh);
    }
}

// ---------------- grid barrier (R3-proven) -----------------------------------
__device__ __forceinline__ void grid_barrier(unsigned& gen) {
    __syncthreads();
    if (threadIdx.x == 0) {
        __threadfence();
        unsigned arr = atomicAdd(&g_bar_count, 1u);
        if (arr == NCTA - 1) {
            g_bar_count = 0;
            __threadfence();
            atomicExch(&g_bar_gen, gen + 1);
        } else {
            unsigned g;
            do {
                asm volatile("ld.acquire.gpu.u32 %0, [%1];"
                             : "=r"(g) : "l"(&g_bar_gen) : "memory");
            } while (g == gen);
        }
        __threadfence();
    }
    gen++;
    __syncthreads();
}

// ---------------- reset ------------------------------------------------------
__global__ void reset_kernel() {
    int i = blockIdx.x * blockDim.x + threadIdx.x;
    if (i < HID * BATCH) g_h[0][i] = 0.0f;
    if (i < 16 * 2 * 4096) g_hB[0][i] = __float2bfloat16(0.0f);
    if (i < CLS * BATCH) g_tf[i] = 0.0f;
    if (i == 0) { g_bar_count = 0; g_bar_gen = 0; g_tf_flag = 0; }
}

// ---------------- persistent kernel -----------------------------------------
__global__ __launch_bounds__(NTHR, 1) void tfcrnn_persistent(
    const float* __restrict__ x, const float* __restrict__ y,
    const int* __restrict__ rand_vals, const float* __restrict__ W_ih,
    const float* __restrict__ W_hh, const float* __restrict__ b_ih,
    const float* __restrict__ b_hh, const float* __restrict__ W_cls,
    const float* __restrict__ b_cls, float* __restrict__ out) {
    extern __shared__ __align__(128) char smem[];
    const int tid = threadIdx.x;
    const int lane = tid & 31;
    const int wid = tid >> 5;   // 0..11
    const int cta = blockIdx.x;
    const int mt = wid % 3;     // m-tile (gate): 0=R 1=Z 2=N
    const int nt = wid / 3;     // n-tile (batch block of 8)
    unsigned gen = 0;
    uint32_t sb;
    asm("{ .reg .u64 t; cvta.to.shared.u64 t, %1; cvt.u32.u64 %0, t; }"
        : "=r"(sb) : "l"(smem));

    // per-lane ldmatrix offsets
    const uint32_t aoff =
        ((lane & 7) + 8 * ((lane >> 3) & 1)) * 272 + (lane >> 4) * 16 +
        mt * 4352;  // + mt*16 rows
    const uint32_t boff = (lane & 7) * 272 + ((lane >> 3) & 1) * 16 + nt * 2176;

    // ---- one-time: prepack W hi/lo into per-chunk row-major planes ----
    for (int idx = tid; idx < 48 * 2304; idx += NTHR) {
        int r = idx / 2304, k = idx % 2304;
        int gate = r >> 4, u = cta * 16 + (r & 15);
        float w = (k < HID) ? W_hh[(size_t)(gate * HID + u) * HID + k]
                            : W_ih[(size_t)(gate * HID + u) * 272 + (k - HID)];
        __nv_bfloat16 hi = __float2bfloat16(w);
        __nv_bfloat16 lo = __float2bfloat16(w - __bfloat162float(hi));
        int ch = k >> 7, kl = k & 127;
        size_t base = ((size_t)(cta * NCH + ch) * 2) * 6144 + r * 128 + kl;
        g_wA[base] = hi;
        g_wA[base + 6144] = lo;
    }
    // ---- one-time: x -> bf16 hi/lo chunk planes (split across grid) ----
    for (size_t o = (size_t)cta * NTHR + tid; o < (size_t)TSTEPS * INF * BATCH;
         o += (size_t)NCTA * NTHR) {
        int b = (int)(o & 31), k = (int)((o >> 5) & 255), tt = (int)(o >> 13);
        float v = x[((size_t)b * TSTEPS + tt) * INF + k];
        __nv_bfloat16 hi = __float2bfloat16(v);
        __nv_bfloat16 lo = __float2bfloat16(v - __bfloat162float(hi));
        int cx = k >> 7, kl = k & 127;
        size_t base = ((size_t)(tt * 2 + cx) * 2) * 4096 + b * 128 + kl;
        g_xB[base] = hi;
        g_xB[base + 4096] = lo;
    }
    grid_barrier(gen);

    float* spf = (float*)(smem + SP);
    float* scls = (float*)(smem + SCLS);
    const float4* wA4 = (const float4*)g_wA;
    const float4* xB4 = (const float4*)g_xB;

    for (int t = 0; t < TSTEPS; t++) {
        const float4* hB4 = (const float4*)g_hB[t & 1];

        float dH[4] = {0, 0, 0, 0}, dX[4] = {0, 0, 0, 0};

        // prologue: LDG chunk 0 into regs
        float4 ntA[4], ntB[3];
        {
            size_t ab = (size_t)(cta * NCH) * 1536;
#pragma unroll
            for (int j = 0; j < 4; j++) ntA[j] = wA4[ab + tid + j * NTHR];
#pragma unroll
            for (int j = 0; j < 3; j++) {
                int idx = tid + j * NTHR;
                if (idx < 1024) ntB[j] = hB4[idx];  // chunk 0 = h chunk 0
            }
        }

        // ---- chunk loop: single-sync double buffer ----
        for (int ch = 0; ch < NCH; ch++) {
            const int p = ch & 1;
            // STS chunk ch
#pragma unroll
            for (int j = 0; j < 4; j++) {
                int idx = tid + j * NTHR;
                int plane = idx >> 9;  // /768
                if (idx >= 768) plane = 1;
                int rem = idx - plane * 768;
                int row = rem >> 4, k16 = rem & 15;
                *(float4*)(smem + SA(p, plane) + row * 272 + k16 * 16) = ntA[j];
            }
#pragma unroll
            for (int j = 0; j < 3; j++) {
                int idx = tid + j * NTHR;
                if (idx < 1024) {
                    int plane = idx >> 9;
                    int rem = idx - plane * 512;
                    int row = rem >> 4, k16 = rem & 15;
                    *(float4*)(smem + SB(p, plane) + row * 272 + k16 * 16) =
                        ntB[j];
                }
            }
            __syncthreads();
            // LDG chunk ch+1
            if (ch + 1 < NCH) {
                const int nc = ch + 1;
                size_t ab = (size_t)(cta * NCH + nc) * 1536;
#pragma unroll
                for (int j = 0; j < 4; j++) ntA[j] = wA4[ab + tid + j * NTHR];
#pragma unroll
                for (int j = 0; j < 3; j++) {
                    int idx = tid + j * NTHR;
                    if (idx < 1024) {
                        if (nc < 16)
                            ntB[j] = hB4[(size_t)nc * 1024 + idx];
                        else
                            ntB[j] = xB4[(size_t)(t * 2 + (nc - 16)) * 1024 +
                                         idx];
                    }
                }
            }
            // compute chunk ch
            chunk_mma(sb + SA(p, 0) + aoff, sb + SA(p, 1) + aoff,
                      sb + SB(p, 0) + boff, sb + SB(p, 1) + boff,
                      (ch < 16) ? dH : dX);
        }
        __syncthreads();  // A/B buffers done; reuse smem region? (sp separate)

        // ---- writeout D fragments to sp ----
        {
            int r0 = lane >> 2, c0 = (lane & 3) * 2;
            int col = nt * 8 + c0;
            if (mt < 2) {
                spf[(mt * 16 + r0) * 32 + col] = dH[0] + dX[0];
                spf[(mt * 16 + r0) * 32 + col + 1] = dH[1] + dX[1];
                spf[(mt * 16 + r0 + 8) * 32 + col] = dH[2] + dX[2];
                spf[(mt * 16 + r0 + 8) * 32 + col + 1] = dH[3] + dX[3];
            } else {
                spf[(32 + r0) * 32 + col] = dH[0];
                spf[(32 + r0) * 32 + col + 1] = dH[1];
                spf[(32 + r0 + 8) * 32 + col] = dH[2];
                spf[(32 + r0 + 8) * 32 + col + 1] = dH[3];
                spf[(48 + r0) * 32 + col] = dX[0];
                spf[(48 + r0) * 32 + col + 1] = dX[1];
                spf[(48 + r0 + 8) * 32 + col] = dX[2];
                spf[(48 + r0 + 8) * 32 + col + 1] = dX[3];
            }
        }
        __syncthreads();

        // ---- wait for tf(t-1) (hidden under GEMM above) ----
        if (tid == 0) {
            unsigned thr = 16u * (unsigned)t, v;
            do {
                asm volatile("ld.acquire.gpu.u32 %0, [%1];"
                             : "=r"(v) : "l"(&g_tf_flag) : "memory");
            } while (v < thr);
            __threadfence();
        }
        __syncthreads();

        // ---- finalize: gates + tf + biases + state update ----
        const float* hcur = g_h[t & 1];
        float* hnxt = g_h[(t + 1) & 1];
        __nv_bfloat16* hBn = g_hB[(t + 1) & 1];
        for (int it = tid; it < 16 * BATCH; it += NTHR) {
            const int ul = it >> 5, b = it & 31;
            const int u = cta * 16 + ul;
            float sR = spf[ul * 32 + b];
            float sZ = spf[(16 + ul) * 32 + b];
            float hN = spf[(32 + ul) * 32 + b];
            float iN = spf[(48 + ul) * 32 + b];
#pragma unroll
            for (int j = 0; j < CLS; j++) {
                float tfv = g_tf[j * 32 + b];
                sR = fmaf(tfv, W_ih[(size_t)u * 272 + 256 + j], sR);
                sZ = fmaf(tfv, W_ih[(size_t)(HID + u) * 272 + 256 + j], sZ);
                iN = fmaf(tfv, W_ih[(size_t)(2 * HID + u) * 272 + 256 + j], iN);
            }
            sR += b_ih[u] + b_hh[u];
            sZ += b_ih[HID + u] + b_hh[HID + u];
            iN += b_ih[2 * HID + u];
            hN += b_hh[2 * HID + u];
            float hp = hcur[(size_t)u * 32 + b];
            float r = sigmoidf_(sR);
            float z = sigmoidf_(sZ);
            float n = tanhf(iN + r * hN);
            float hn = (1.0f - z) * n + z * hp;
            hnxt[(size_t)u * 32 + b] = hn;
            __nv_bfloat16 hi = __float2bfloat16(hn);
            __nv_bfloat16 lo = __float2bfloat16(hn - __bfloat162float(hi));
            size_t base = ((size_t)(u >> 7) * 2) * 4096 + b * 128 + (u & 127);
            hBn[base] = hi;
            hBn[base + 4096] = lo;
        }

        grid_barrier(gen);  // h(t) complete & visible

        // ---- classifier + teacher forcing: CTA c < 16 owns class c ----
        if (cta < CLS) {
            const int c = cta;
            const float* hv = g_h[(t + 1) & 1];
            if (wid < 8) {
                float a0 = 0.0f, a1 = 0.0f;
                const int ub = wid * 256;
#pragma unroll 8
                for (int u = ub; u < ub + 256; u += 2) {
                    a0 = fmaf(hv[(size_t)u * 32 + lane],
                              W_cls[(size_t)c * HID + u], a0);
                    a1 = fmaf(hv[(size_t)(u + 1) * 32 + lane],
                              W_cls[(size_t)c * HID + u + 1], a1);
                }
                scls[wid * 32 + lane] = a0 + a1;
            }
            __syncthreads();
            if (wid == 0) {
                float tot = b_cls[c];
#pragma unroll
                for (int w = 0; w < 8; w++) tot += scls[w * 32 + lane];
                const int b = lane;
                out[((size_t)b * TSTEPS + t) * CLS + c] = tot;
                float pred = (tot > 0.0f) ? 1.0f : 0.0f;
                bool fl = rand_vals[t * BATCH + b] < 900;
                g_tf[c * 32 + b] =
                    fl ? y[((size_t)b * TSTEPS + t) * CLS + c] : pred;
            }
            __syncthreads();
            if (tid == 0) {
                __threadfence();
                atomicAdd(&g_tf_flag, 1u);
            }
        }
    }
}

// ---------------- launch ----------------------------------------------------
extern "C" void kernel_launch(void* const* d_in, const int* in_sizes, int n_in,
                              void* d_out, int out_size) {
    const float* x     = (const float*)d_in[0];
    const float* y     = (const float*)d_in[1];
    const int*   rv    = (const int*)d_in[2];
    const float* W_ih  = (const float*)d_in[3];
    const float* W_hh  = (const float*)d_in[4];
    const float* b_ih  = (const float*)d_in[5];
    const float* b_hh  = (const float*)d_in[6];
    const float* W_cls = (const float*)d_in[7];
    const float* b_cls = (const float*)d_in[8];
    float* out = (float*)d_out;

    cudaFuncSetAttribute(tfcrnn_persistent,
                         cudaFuncAttributeMaxDynamicSharedMemorySize, SMEM_SZ);

    reset_kernel<<<256, 512>>>();
    tfcrnn_persistent<<<NCTA, NTHR, SMEM_SZ>>>(x, y, rv, W_ih, W_hh, b_ih,
                                               b_hh, W_cls, b_cls, out);
}